// round 10
// baseline (speedup 1.0000x reference)
#include <cuda_runtime.h>

#define NB 32
#define GRID_N 128
#define CIN 32
#define COUT 32
#define TDIM 256
#define MM 17
#define KY_TOT 34   // 17 top rows + 17 bottom rows

// Scratch (allocation-free): device globals.
__device__ float2 g_X1[NB * MM * GRID_N * CIN];   // [(b*17+kx)*128+y]*32+c
__device__ float2 g_Y1[NB * GRID_N * MM * COUT];  // [(b*128+y)*17+kx]*32+o
__device__ float2 g_TS[NB * KY_TOT];

// Precomputed twiddle tables (built once per launch by k_tables; blocks copy
// these to smem with cheap float4 loads instead of per-block sincospif, which
// was MUFU-throughput-bound at ~2k cycles/block).
__device__ float4 g_T1 [MM * 32];   // K1:      [kx][j] xi=2j+1 / 2j+2
__device__ float4 g_T2a[18 * 32];   // K2 st1:  [g][j]  yy=2j+1 / 2j+2
__device__ float4 g_T2b[65 * 9];    // K2 st3:  [yy][j] modes 2j+1 / 2j+2 (j=8: 17)
__device__ float4 g_T3 [65 * 8];    // K3:      [xx][j] modes 2j+1 / 2j+2

// ---------------------------------------------------------------------------
// Setup: build all twiddle tables once (grid-strided; deterministic).
// ---------------------------------------------------------------------------
__global__ void k_tables() {
    int tid = blockIdx.x * blockDim.x + threadIdx.x;
    int stride = gridDim.x * blockDim.x;

    for (int i = tid; i < MM * 32; i += stride) {
        int kx = i >> 5, j = i & 31;
        float s1, c1, s2 = 0.f, c2 = 0.f;
        sincospif((float)(kx * (2 * j + 1)) * (1.0f / 64.0f), &s1, &c1);
        if (j < 31) sincospif((float)(kx * (2 * j + 2)) * (1.0f / 64.0f), &s2, &c2);
        g_T1[i] = make_float4(c1, s1, c2, s2);
    }
    for (int i = tid; i < 18 * 32; i += stride) {
        int g = i >> 5, j = i & 31;
        float s1, c1, s2 = 0.f, c2 = 0.f;
        sincospif((float)(g * (2 * j + 1)) * (1.0f / 64.0f), &s1, &c1);
        if (j < 31) sincospif((float)(g * (2 * j + 2)) * (1.0f / 64.0f), &s2, &c2);
        g_T2a[i] = make_float4(c1, s1, c2, s2);
    }
    for (int i = tid; i < 65 * 9; i += stride) {
        int yy = i / 9, j = i - yy * 9;
        float s1, c1, s2 = 0.f, c2 = 0.f;
        int p1 = (j < 8) ? (2 * j + 1) : 17;
        sincospif((float)(p1 * yy) * (1.0f / 64.0f), &s1, &c1);
        if (j < 8) sincospif((float)((2 * j + 2) * yy) * (1.0f / 64.0f), &s2, &c2);
        g_T2b[i] = make_float4(c1, s1, c2, s2);
    }
    for (int i = tid; i < 65 * 8; i += stride) {
        int xx = i >> 3, j = i & 7;
        float sA, cA, sB, cB;
        sincospif((float)((2 * j + 1) * xx) * (1.0f / 64.0f), &sA, &cA);
        sincospif((float)((2 * j + 2) * xx) * (1.0f / 64.0f), &sB, &cB);
        g_T3[i] = make_float4(cA, sA, cB, sB);
    }
}

// ---------------------------------------------------------------------------
// K0: time-modulation scales  t1 = t_emb @ (k1r + i k1i), t2 likewise. (B,17)
// ---------------------------------------------------------------------------
__global__ void k0_tscale(const float* __restrict__ t_emb,
                          const float* __restrict__ k1r, const float* __restrict__ k1i,
                          const float* __restrict__ k2r, const float* __restrict__ k2i) {
    int b = blockIdx.x;
    int tid = threadIdx.x;           // 64 threads
    int which = tid >> 5;
    int m = tid & 31;
    if (m >= MM) return;
    const float* kr = which ? k2r : k1r;
    const float* ki = which ? k2i : k1i;
    const float* te = t_emb + b * TDIM;
    float ar = 0.f, ai = 0.f;
    #pragma unroll 4
    for (int d = 0; d < TDIM; ++d) {
        float v = te[d];
        ar += v * kr[d * MM + m];
        ai += v * ki[d * MM + m];
    }
    g_TS[b * KY_TOT + which * MM + m] = make_float2(ar, ai);
}

// ---------------------------------------------------------------------------
// K1: partial DFT over x (real input), 17 modes, scale 1/16384.
// x<->128-x pairing; ONE kx per thread; float4-packed twiddles from gmem.
// PARTIAL unroll (8) to keep live registers bounded.
// ---------------------------------------------------------------------------
__global__ void __launch_bounds__(256) k1_dftx(const float* __restrict__ x) {
    __shared__ float2 sP[64 * CIN];    // (ve,vo); row0 = (xs0+xs64, xs0-xs64). 16KB
    __shared__ float4 T1p[MM * 32];    // copied from g_T1
    int b = blockIdx.x >> 7, y = blockIdx.x & 127;
    int tid = threadIdx.x;

    const float* xrow = x + (size_t)(b * GRID_N + y) * GRID_N * CIN;
    for (int i = tid; i < 64 * CIN; i += 256) {
        int xi = i >> 5, c = i & 31;
        int xp = (xi == 0) ? 64 : (128 - xi);
        float a  = xrow[xi * CIN + c];
        float bb = xrow[xp * CIN + c];
        sP[i] = make_float2(a + bb, a - bb);
    }
    for (int i = tid; i < MM * 32; i += 256) T1p[i] = g_T1[i];
    __syncthreads();

    const float scale = 1.0f / 16384.0f;
    for (int idx = tid; idx < MM * CIN; idx += 256) {
        int kx = idx >> 5, c = idx & 31;
        float2 p0 = sP[c];
        float ar = (kx & 1) ? p0.y : p0.x;
        float ai = 0.f;
        const float4* T = &T1p[kx * 32];
        const float2* P = &sP[CIN + c];
        #pragma unroll 8
        for (int j = 0; j < 31; ++j) {
            float4 w = T[j];                   // warp-uniform broadcast
            float2 p1 = P[(2 * j) * CIN];      // xi = 2j+1
            float2 p2 = P[(2 * j + 1) * CIN];  // xi = 2j+2
            ar += p1.x * w.x;  ai -= p1.y * w.y;
            ar += p2.x * w.z;  ai -= p2.y * w.w;
        }
        {   // xi = 63
            float4 w = T[31];
            float2 p = P[62 * CIN];
            ar += p.x * w.x;  ai -= p.y * w.y;
        }
        g_X1[((b * MM + kx) * GRID_N + y) * CIN + c] =
            make_float2(ar * scale, ai * scale);
    }
}

// ---------------------------------------------------------------------------
// K2 (fused, dynamic smem): per (b, kx):
//  stage1: paired DFT over y -> 34 kept rows; groups (g, 34-g) share one
//          twiddle row (sin sign flip): 4 partial sums emit BOTH rows.
//  stage2: complex 32x32 channel mix + time scale
//  stage3: paired inverse DFT, S/D from shared, float4 twiddles
// Twiddle tables copied from gmem (no per-block sincospif).
// ---------------------------------------------------------------------------
// dynamic smem (bytes):
//  [0,32768)      phase A: PA float4[64*32]  (ae.re, ae.im, ao.re, ao.im)
//                 phase B aliases: sZ  float2[34*32] @0      (8704)
//                                  sSD float4[17*32] @8704   (8704)
//                                  T3p float4[65*9]  @17408  (9360)
//  [32768,41984)  T1p float4[18*32]
//  [41984,50688)  sX2 float2[34*32]
//  [50688,50960)  sT  float2[34]
#define K2_SMEM_BYTES 50960

__global__ void __launch_bounds__(256) k2_mid(
        const float* __restrict__ w1r, const float* __restrict__ w1i,
        const float* __restrict__ w2r, const float* __restrict__ w2i) {
    extern __shared__ char smemraw[];
    float4* PA  = (float4*)(smemraw);
    float4* T1p = (float4*)(smemraw + 32768);
    float2* sX2 = (float2*)(smemraw + 41984);
    float2* sT  = (float2*)(smemraw + 50688);
    float2* sZ  = (float2*)(smemraw);            // phase B
    float4* sSD = (float4*)(smemraw + 8704);     // [p-1][o]: (S.re,S.im,D.re,D.im)
    float4* T3p = (float4*)(smemraw + 17408);    // [yy][j]

    int b  = blockIdx.x / MM;
    int kx = blockIdx.x % MM;
    int tid = threadIdx.x;

    const float2* src = g_X1 + (size_t)(b * MM + kx) * GRID_N * CIN;
    for (int i = tid; i < 64 * CIN; i += 256) {
        int yy = i >> 5, c = i & 31;
        int yp = (yy == 0) ? 64 : (128 - yy);
        float2 a = src[yy * CIN + c];
        float2 d = src[yp * CIN + c];
        PA[i] = make_float4(a.x + d.x, a.y + d.y, a.x - d.x, a.y - d.y);
    }
    for (int i = tid; i < 18 * 32; i += 256) T1p[i] = g_T2a[i];
    if (tid < KY_TOT) sT[tid] = g_TS[b * KY_TOT + tid];
    __syncthreads();

    // ---- stage 1: paired DFT over y; groups g=0..17 emit rows (g, 34-g) ----
    for (int idx = tid; idx < 18 * 32; idx += 256) {
        int g = idx >> 5, c = idx & 31;
        const float4* T = &T1p[g * 32];
        const float4* P = &PA[CIN + c];
        float u1 = 0.f, u2 = 0.f, u3 = 0.f, u4 = 0.f;
        #pragma unroll 4
        for (int j = 0; j < 31; ++j) {
            float4 w = T[j];
            float4 p1 = P[(2 * j) * CIN];      // yy = 2j+1
            float4 p2 = P[(2 * j + 1) * CIN];  // yy = 2j+2
            u1 += p1.x * w.x;  u2 += p1.w * w.y;
            u3 += p1.y * w.x;  u4 += p1.z * w.y;
            u1 += p2.x * w.z;  u2 += p2.w * w.w;
            u3 += p2.y * w.z;  u4 += p2.z * w.w;
        }
        {   // yy = 63
            float4 w = T1p[g * 32 + 31];
            float4 p = P[62 * CIN];
            u1 += p.x * w.x;  u2 += p.w * w.y;
            u3 += p.y * w.x;  u4 += p.z * w.y;
        }
        float4 p0 = PA[c];
        float br = (g & 1) ? p0.z : p0.x;
        float bi = (g & 1) ? p0.w : p0.y;
        if (g <= 16)
            sX2[g * CIN + c]        = make_float2(br + u1 + u2, bi + u3 - u4);
        if (g >= 1)
            sX2[(34 - g) * CIN + c] = make_float2(br + u1 - u2, bi + u3 + u4);
    }
    __syncthreads();

    // ---- stage 2: complex channel mix + time scale -> sZ (aliases PA) ----
    for (int idx = tid; idx < KY_TOT * COUT; idx += 256) {
        int kyi = idx >> 5, o = idx & 31;
        const float* wr; const float* wi; int iw;
        if (kyi < MM) { wr = w1r; wi = w1i; iw = kyi; }
        else          { wr = w2r; wi = w2i; iw = kyi - MM; }
        size_t base = ((size_t)(iw * MM + kx) * CIN) * COUT + o;
        float ar = 0.f, ai = 0.f;
        #pragma unroll 8
        for (int c = 0; c < CIN; ++c) {
            float2 a = sX2[kyi * CIN + c];
            float wre = wr[base + (size_t)c * COUT];
            float wim = wi[base + (size_t)c * COUT];
            ar += a.x * wre - a.y * wim;
            ai += a.x * wim + a.y * wre;
        }
        float2 ts = sT[kyi];
        sZ[idx] = make_float2(ar * ts.x - ai * ts.y, ar * ts.y + ai * ts.x);
    }
    // stage-3 packed table (aliases dead PA region, disjoint from sZ/sSD)
    for (int i = tid; i < 65 * 9; i += 256) T3p[i] = g_T2b[i];
    __syncthreads();

    // ---- S/D mode pairs: modes p=1..16 pair with (34-p); p=17 unpaired ----
    for (int i = tid; i < MM * 32; i += 256) {
        int p = (i >> 5) + 1, o = i & 31;
        float2 zp = sZ[p * COUT + o];
        float4 sd;
        if (p < MM) {
            float2 zq = sZ[(34 - p) * COUT + o];
            sd = make_float4(zp.x + zq.x, zp.y + zq.y, zp.x - zq.x, zp.y - zq.y);
        } else {
            sd = make_float4(zp.x, zp.y, -zp.x, -zp.y);
        }
        sSD[i] = sd;
    }
    __syncthreads();

    // ---- stage 3: Y[y] = E + F, Y[128-y] = E - F (S/D from shared) ----
    {
        int o = tid & 31, yg = tid >> 5;
        float2 z0 = sZ[o];
        const float4* SD = &sSD[o];
        for (int yy = yg; yy <= 64; yy += 8) {
            const float4* T = &T3p[yy * 9];
            float er = z0.x, ei = z0.y, fr = 0.f, fi = 0.f;
            #pragma unroll 4
            for (int j = 0; j < 8; ++j) {
                float4 w = T[j];                 // warp-uniform broadcast
                float4 a  = SD[(2 * j) * 32];
                float4 b2 = SD[(2 * j + 1) * 32];
                er += a.x * w.x;   ei += a.y * w.x;
                fr -= a.w * w.y;   fi += a.z * w.y;
                er += b2.x * w.z;  ei += b2.y * w.z;
                fr -= b2.w * w.w;  fi += b2.z * w.w;
            }
            {   // mode 17
                float4 w = T[8];
                float4 a = SD[16 * 32];
                er += a.x * w.x;  ei += a.y * w.x;
                fr -= a.w * w.y;  fi += a.z * w.y;
            }
            g_Y1[(((size_t)b * GRID_N + yy) * MM + kx) * COUT + o] =
                make_float2(er + fr, ei + fi);
            if (yy >= 1 && yy < 64)
                g_Y1[(((size_t)b * GRID_N + (128 - yy)) * MM + kx) * COUT + o] =
                    make_float2(er - fr, ei - fi);
        }
    }
}

// ---------------------------------------------------------------------------
// K3: inverse over x (irfft C2R), output pairing, ONE y-row per block,
// float4-packed twiddles copied from gmem (no per-block sincospif).
//   out[x] = E+O, out[128-x] = E-O
// ---------------------------------------------------------------------------
__global__ void __launch_bounds__(256) k3_idftx(float* __restrict__ out) {
    __shared__ float2 sY[MM * COUT];   // 4.25 KB
    __shared__ float4 T3[65 * 8];      // copied from g_T3
    int b = blockIdx.x >> 7, y = blockIdx.x & 127;
    int tid = threadIdx.x;

    const float2* src = g_Y1 + (size_t)(b * GRID_N + y) * MM * COUT;
    for (int i = tid; i < MM * COUT; i += 256) sY[i] = src[i];
    for (int i = tid; i < 65 * 8; i += 256) T3[i] = g_T3[i];
    __syncthreads();

    int o  = tid & 31;
    int xg = tid >> 5;   // 0..7

    float yr[MM], yi[MM];
    yr[0] = sY[o].x;     // Im of bin 0 ignored (C2R); bin 64 is zero
    yi[0] = 0.f;
    #pragma unroll
    for (int k = 1; k < MM; ++k) {
        float2 v = sY[k * COUT + o];
        yr[k] = 2.f * v.x;
        yi[k] = 2.f * v.y;
    }

    float* orow = out + (size_t)(b * GRID_N + y) * GRID_N * COUT;
    for (int xx = xg; xx <= 64; xx += 8) {
        float E = yr[0], O = 0.f;
        const float4* T = &T3[xx * 8];
        #pragma unroll
        for (int j = 0; j < 8; ++j) {
            float4 w = T[j];            // warp-uniform broadcast, imm offsets
            int ka = 2 * j + 1, kb = 2 * j + 2;
            E += yr[ka] * w.x;  O -= yi[ka] * w.y;
            E += yr[kb] * w.z;  O -= yi[kb] * w.w;
        }
        orow[(size_t)xx * COUT + o] = E + O;
        if (xx >= 1 && xx < 64)
            orow[(size_t)(128 - xx) * COUT + o] = E - O;
    }
}

// ---------------------------------------------------------------------------
extern "C" void kernel_launch(void* const* d_in, const int* in_sizes, int n_in,
                              void* d_out, int out_size) {
    const float* x     = (const float*)d_in[0];
    const float* t_emb = (const float*)d_in[1];
    const float* w1r   = (const float*)d_in[2];
    const float* w1i   = (const float*)d_in[3];
    const float* w2r   = (const float*)d_in[4];
    const float* w2i   = (const float*)d_in[5];
    const float* k1r   = (const float*)d_in[6];
    const float* k1i   = (const float*)d_in[7];
    const float* k2r   = (const float*)d_in[8];
    const float* k2i   = (const float*)d_in[9];
    float* out = (float*)d_out;

    cudaFuncSetAttribute(k2_mid, cudaFuncAttributeMaxDynamicSharedMemorySize,
                         K2_SMEM_BYTES);

    k_tables <<<32, 256>>>();
    k0_tscale<<<NB, 64>>>(t_emb, k1r, k1i, k2r, k2i);
    k1_dftx  <<<NB * GRID_N, 256>>>(x);
    k2_mid   <<<NB * MM, 256, K2_SMEM_BYTES>>>(w1r, w1i, w2r, w2i);
    k3_idftx <<<NB * GRID_N, 256>>>(out);
}

// round 11
// speedup vs baseline: 1.2015x; 1.2015x over previous
#include <cuda_runtime.h>

#define NB 32
#define GRID_N 128
#define CIN 32
#define COUT 32
#define TDIM 256
#define MM 17
#define KY_TOT 34   // 17 top rows + 17 bottom rows

// Scratch (allocation-free): device globals.
__device__ float2 g_X1[NB * MM * GRID_N * CIN];   // [(b*17+kx)*128+y]*32+c
__device__ float2 g_Y1[NB * GRID_N * MM * COUT];  // [(b*128+y)*17+kx]*32+o
__device__ float2 g_TS[NB * KY_TOT];

// Precomputed twiddle tables (built once per launch).
// Paired layouts: one float4 holds (cos,sin) for TWO modes at one sample.
__device__ float4 g_T1v[9 * 63];    // K1:  [pair][xi-1] = (c,s)@kx=2p, (c,s)@kx=2p+1 (p=8: 16,16)
__device__ float4 g_T2v[9 * 63];    // K2s1:[pair][yy-1] = (c,s)@g=2q, (c,s)@g=2q+1 (q=8: 16,17)
__device__ float4 g_T2b[65 * 9];    // K2s3:[yy][j] modes 2j+1 / 2j+2 (j=8: mode 17)
__device__ float4 g_T3 [65 * 8];    // K3:  [xx][j] modes 2j+1 / 2j+2

__global__ void k_tables() {
    int tid = blockIdx.x * blockDim.x + threadIdx.x;
    int stride = gridDim.x * blockDim.x;

    for (int i = tid; i < 9 * 63; i += stride) {
        int p = i / 63, xi = i - p * 63 + 1;
        int kx0 = 2 * p, kx1 = (p < 8) ? (2 * p + 1) : 16;
        float s0, c0, s1, c1;
        sincospif((float)(kx0 * xi) * (1.0f / 64.0f), &s0, &c0);
        sincospif((float)(kx1 * xi) * (1.0f / 64.0f), &s1, &c1);
        g_T1v[i] = make_float4(c0, s0, c1, s1);
    }
    for (int i = tid; i < 9 * 63; i += stride) {
        int q = i / 63, yy = i - q * 63 + 1;
        int g0 = 2 * q, g1 = (q < 8) ? (2 * q + 1) : 17;
        float s0, c0, s1, c1;
        sincospif((float)(g0 * yy) * (1.0f / 64.0f), &s0, &c0);
        sincospif((float)(g1 * yy) * (1.0f / 64.0f), &s1, &c1);
        g_T2v[i] = make_float4(c0, s0, c1, s1);
    }
    for (int i = tid; i < 65 * 9; i += stride) {
        int yy = i / 9, j = i - yy * 9;
        float s1, c1, s2 = 0.f, c2 = 0.f;
        int p1 = (j < 8) ? (2 * j + 1) : 17;
        sincospif((float)(p1 * yy) * (1.0f / 64.0f), &s1, &c1);
        if (j < 8) sincospif((float)((2 * j + 2) * yy) * (1.0f / 64.0f), &s2, &c2);
        g_T2b[i] = make_float4(c1, s1, c2, s2);
    }
    for (int i = tid; i < 65 * 8; i += stride) {
        int xx = i >> 3, j = i & 7;
        float sA, cA, sB, cB;
        sincospif((float)((2 * j + 1) * xx) * (1.0f / 64.0f), &sA, &cA);
        sincospif((float)((2 * j + 2) * xx) * (1.0f / 64.0f), &sB, &cB);
        g_T3[i] = make_float4(cA, sA, cB, sB);
    }
}

// ---------------------------------------------------------------------------
// K0: time-modulation scales  t1 = t_emb @ (k1r + i k1i), t2 likewise. (B,17)
// ---------------------------------------------------------------------------
__global__ void k0_tscale(const float* __restrict__ t_emb,
                          const float* __restrict__ k1r, const float* __restrict__ k1i,
                          const float* __restrict__ k2r, const float* __restrict__ k2i) {
    int b = blockIdx.x;
    int tid = threadIdx.x;           // 64 threads
    int which = tid >> 5;
    int m = tid & 31;
    if (m >= MM) return;
    const float* kr = which ? k2r : k1r;
    const float* ki = which ? k2i : k1i;
    const float* te = t_emb + b * TDIM;
    float ar = 0.f, ai = 0.f;
    #pragma unroll 4
    for (int d = 0; d < TDIM; ++d) {
        float v = te[d];
        ar += v * kr[d * MM + m];
        ai += v * ki[d * MM + m];
    }
    g_TS[b * KY_TOT + which * MM + m] = make_float2(ar, ai);
}

// ---------------------------------------------------------------------------
// K1: partial DFT over x (real input), 17 modes, scale 1/16384.
// 288 threads = 9 warps; warp w computes kx pair (2w, 2w+1) — each LDS.64
// data load feeds 4 FMAs (2 modes). Perfectly balanced: 1 item/thread.
// ---------------------------------------------------------------------------
__global__ void __launch_bounds__(288) k1_dftx(const float* __restrict__ x) {
    __shared__ float2 sP[64 * CIN];    // (ve,vo); row0 = (xs0+xs64, xs0-xs64). 16KB
    __shared__ float4 T1v[9 * 63];     // 9.1KB
    int b = blockIdx.x >> 7, y = blockIdx.x & 127;
    int tid = threadIdx.x;

    const float* xrow = x + (size_t)(b * GRID_N + y) * GRID_N * CIN;
    for (int i = tid; i < 64 * CIN; i += 288) {
        int xi = i >> 5, c = i & 31;
        int xp = (xi == 0) ? 64 : (128 - xi);
        float a  = xrow[xi * CIN + c];
        float bb = xrow[xp * CIN + c];
        sP[i] = make_float2(a + bb, a - bb);
    }
    for (int i = tid; i < 9 * 63; i += 288) T1v[i] = g_T1v[i];
    __syncthreads();

    const float scale = 1.0f / 16384.0f;
    int w = tid >> 5, c = tid & 31;     // w 0..8
    int kx0 = 2 * w;
    float2 p0 = sP[c];
    float ar0 = p0.x, ai0 = 0.f;        // kx0 even -> +xs64 fold
    float ar1 = p0.y, ai1 = 0.f;        // kx1 odd  -> -xs64 fold (w=8: discarded)
    const float4* T = &T1v[w * 63];
    const float2* P = &sP[CIN + c];
    #pragma unroll 7
    for (int j = 0; j < 63; ++j) {
        float4 tw = T[j];               // warp-uniform broadcast (both modes)
        float2 p  = P[j * CIN];         // xi = j+1
        ar0 += p.x * tw.x;  ai0 -= p.y * tw.y;
        ar1 += p.x * tw.z;  ai1 -= p.y * tw.w;
    }
    g_X1[((b * MM + kx0) * GRID_N + y) * CIN + c] =
        make_float2(ar0 * scale, ai0 * scale);
    if (w < 8)
        g_X1[((b * MM + kx0 + 1) * GRID_N + y) * CIN + c] =
            make_float2(ar1 * scale, ai1 * scale);
}

// ---------------------------------------------------------------------------
// K2 (fused, dynamic smem, 288 threads): per (b, kx):
//  stage1: paired DFT over y; warp q computes g-pair (2q, 2q+1), both modes'
//          twiddles in ONE float4 broadcast; each g emits rows (g, 34-g).
//  stage2: complex 32x32 channel mix + time scale
//  stage3: paired inverse DFT, TWO yy per iteration sharing the SD loads.
// ---------------------------------------------------------------------------
// dynamic smem (bytes):
//  [0,32768)      phase A: PA float4[64*32]  (ae.re, ae.im, ao.re, ao.im)
//                 phase B aliases: sZ  float2[34*32] @0      (8704)
//                                  sSD float4[17*32] @8704   (8704)
//                                  T3p float4[65*9]  @17408  (9360)
//  [32768,41984)  T2v float4[9*63] (9072 used)
//  [41984,50688)  sX2 float2[34*32]
//  [50688,50960)  sT  float2[34]
#define K2_SMEM_BYTES 50960

__global__ void __launch_bounds__(288) k2_mid(
        const float* __restrict__ w1r, const float* __restrict__ w1i,
        const float* __restrict__ w2r, const float* __restrict__ w2i) {
    extern __shared__ char smemraw[];
    float4* PA  = (float4*)(smemraw);
    float4* T2v = (float4*)(smemraw + 32768);
    float2* sX2 = (float2*)(smemraw + 41984);
    float2* sT  = (float2*)(smemraw + 50688);
    float2* sZ  = (float2*)(smemraw);            // phase B
    float4* sSD = (float4*)(smemraw + 8704);     // [p-1][o]: (S.re,S.im,D.re,D.im)
    float4* T3p = (float4*)(smemraw + 17408);    // [yy][j]

    int b  = blockIdx.x / MM;
    int kx = blockIdx.x % MM;
    int tid = threadIdx.x;

    const float2* src = g_X1 + (size_t)(b * MM + kx) * GRID_N * CIN;
    for (int i = tid; i < 64 * CIN; i += 288) {
        int yy = i >> 5, c = i & 31;
        int yp = (yy == 0) ? 64 : (128 - yy);
        float2 a = src[yy * CIN + c];
        float2 d = src[yp * CIN + c];
        PA[i] = make_float4(a.x + d.x, a.y + d.y, a.x - d.x, a.y - d.y);
    }
    for (int i = tid; i < 9 * 63; i += 288) T2v[i] = g_T2v[i];
    if (tid < KY_TOT) sT[tid] = g_TS[b * KY_TOT + tid];
    __syncthreads();

    // ---- stage 1: warp q computes g-pair (2q, 2q+1); each g -> rows (g,34-g)
    {
        int q = tid >> 5, c = tid & 31;      // q 0..8
        int g0 = 2 * q;
        int g1 = (q < 8) ? (g0 + 1) : 17;
        const float4* T = &T2v[q * 63];
        const float4* P = &PA[CIN + c];
        float a1 = 0.f, a2 = 0.f, a3 = 0.f, a4 = 0.f;   // g0
        float b1 = 0.f, b2 = 0.f, b3 = 0.f, b4 = 0.f;   // g1
        #pragma unroll 3
        for (int j = 0; j < 63; ++j) {
            float4 w = T[j];                 // (c0,s0,c1,s1) broadcast
            float4 p = P[j * CIN];           // yy = j+1
            a1 += p.x * w.x;  a2 += p.w * w.y;
            a3 += p.y * w.x;  a4 += p.z * w.y;
            b1 += p.x * w.z;  b2 += p.w * w.w;
            b3 += p.y * w.z;  b4 += p.z * w.w;
        }
        float4 p0 = PA[c];
        // g0 (even): base = (p0.x, p0.y)
        sX2[g0 * CIN + c] = make_float2(p0.x + a1 + a2, p0.y + a3 - a4);
        if (g0 >= 1)
            sX2[(34 - g0) * CIN + c] = make_float2(p0.x + a1 - a2, p0.y + a3 + a4);
        // g1 (odd): base = (p0.z, p0.w)
        if (g1 <= 16)
            sX2[g1 * CIN + c] = make_float2(p0.z + b1 + b2, p0.w + b3 - b4);
        sX2[(34 - g1) * CIN + c] = make_float2(p0.z + b1 - b2, p0.w + b3 + b4);
    }
    __syncthreads();

    // ---- stage 2: complex channel mix + time scale -> sZ (aliases PA) ----
    for (int idx = tid; idx < KY_TOT * COUT; idx += 288) {
        int kyi = idx >> 5, o = idx & 31;
        const float* wr; const float* wi; int iw;
        if (kyi < MM) { wr = w1r; wi = w1i; iw = kyi; }
        else          { wr = w2r; wi = w2i; iw = kyi - MM; }
        size_t base = ((size_t)(iw * MM + kx) * CIN) * COUT + o;
        float ar = 0.f, ai = 0.f;
        #pragma unroll 8
        for (int c = 0; c < CIN; ++c) {
            float2 a = sX2[kyi * CIN + c];
            float wre = wr[base + (size_t)c * COUT];
            float wim = wi[base + (size_t)c * COUT];
            ar += a.x * wre - a.y * wim;
            ai += a.x * wim + a.y * wre;
        }
        float2 ts = sT[kyi];
        sZ[idx] = make_float2(ar * ts.x - ai * ts.y, ar * ts.y + ai * ts.x);
    }
    // stage-3 packed table (aliases dead PA region, disjoint from sZ/sSD)
    for (int i = tid; i < 65 * 9; i += 288) T3p[i] = g_T2b[i];
    __syncthreads();

    // ---- S/D mode pairs: modes p=1..16 pair with (34-p); p=17 unpaired ----
    for (int i = tid; i < MM * 32; i += 288) {
        int p = (i >> 5) + 1, o = i & 31;
        float2 zp = sZ[p * COUT + o];
        float4 sd;
        if (p < MM) {
            float2 zq = sZ[(34 - p) * COUT + o];
            sd = make_float4(zp.x + zq.x, zp.y + zq.y, zp.x - zq.x, zp.y - zq.y);
        } else {
            sd = make_float4(zp.x, zp.y, -zp.x, -zp.y);
        }
        sSD[i] = sd;
    }
    __syncthreads();

    // ---- stage 3: TWO yy per iteration share SD loads; Y[y]=E+F, Y[128-y]=E-F
    {
        int o = tid & 31, q = tid >> 5;      // q 0..8
        float2 z0 = sZ[o];
        const float4* SD = &sSD[o];
        for (int yb = q * 2; yb <= 64; yb += 18) {
            int y2ok = (yb + 1 <= 64);
            const float4* Ta = &T3p[yb * 9];
            const float4* Tb = y2ok ? &T3p[(yb + 1) * 9] : Ta;
            float er1 = z0.x, ei1 = z0.y, fr1 = 0.f, fi1 = 0.f;
            float er2 = z0.x, ei2 = z0.y, fr2 = 0.f, fi2 = 0.f;
            #pragma unroll 2
            for (int j = 0; j < 8; ++j) {
                float4 a  = SD[(2 * j) * 32];
                float4 b2 = SD[(2 * j + 1) * 32];
                float4 wA = Ta[j];
                er1 += a.x * wA.x;   ei1 += a.y * wA.x;
                fr1 -= a.w * wA.y;   fi1 += a.z * wA.y;
                er1 += b2.x * wA.z;  ei1 += b2.y * wA.z;
                fr1 -= b2.w * wA.w;  fi1 += b2.z * wA.w;
                float4 wB = Tb[j];
                er2 += a.x * wB.x;   ei2 += a.y * wB.x;
                fr2 -= a.w * wB.y;   fi2 += a.z * wB.y;
                er2 += b2.x * wB.z;  ei2 += b2.y * wB.z;
                fr2 -= b2.w * wB.w;  fi2 += b2.z * wB.w;
            }
            {   // mode 17
                float4 a  = SD[16 * 32];
                float4 wA = Ta[8];
                er1 += a.x * wA.x;  ei1 += a.y * wA.x;
                fr1 -= a.w * wA.y;  fi1 += a.z * wA.y;
                float4 wB = Tb[8];
                er2 += a.x * wB.x;  ei2 += a.y * wB.x;
                fr2 -= a.w * wB.y;  fi2 += a.z * wB.y;
            }
            size_t rb = ((size_t)b * GRID_N) * MM * COUT + (size_t)kx * COUT + o;
            g_Y1[rb + (size_t)yb * MM * COUT] = make_float2(er1 + fr1, ei1 + fi1);
            if (yb >= 1 && yb < 64)
                g_Y1[rb + (size_t)(128 - yb) * MM * COUT] =
                    make_float2(er1 - fr1, ei1 - fi1);
            if (y2ok) {
                int y2 = yb + 1;                   // 1..63 -> both outputs
                g_Y1[rb + (size_t)y2 * MM * COUT] = make_float2(er2 + fr2, ei2 + fi2);
                g_Y1[rb + (size_t)(128 - y2) * MM * COUT] =
                    make_float2(er2 - fr2, ei2 - fi2);
            }
        }
    }
}

// ---------------------------------------------------------------------------
// K3: inverse over x (irfft C2R), output pairing, ONE y-row per block,
// float4-packed twiddles copied from gmem.
//   out[x] = E+O, out[128-x] = E-O
// ---------------------------------------------------------------------------
__global__ void __launch_bounds__(256) k3_idftx(float* __restrict__ out) {
    __shared__ float2 sY[MM * COUT];   // 4.25 KB
    __shared__ float4 T3[65 * 8];      // copied from g_T3
    int b = blockIdx.x >> 7, y = blockIdx.x & 127;
    int tid = threadIdx.x;

    const float2* src = g_Y1 + (size_t)(b * GRID_N + y) * MM * COUT;
    for (int i = tid; i < MM * COUT; i += 256) sY[i] = src[i];
    for (int i = tid; i < 65 * 8; i += 256) T3[i] = g_T3[i];
    __syncthreads();

    int o  = tid & 31;
    int xg = tid >> 5;   // 0..7

    float yr[MM], yi[MM];
    yr[0] = sY[o].x;     // Im of bin 0 ignored (C2R); bin 64 is zero
    yi[0] = 0.f;
    #pragma unroll
    for (int k = 1; k < MM; ++k) {
        float2 v = sY[k * COUT + o];
        yr[k] = 2.f * v.x;
        yi[k] = 2.f * v.y;
    }

    float* orow = out + (size_t)(b * GRID_N + y) * GRID_N * COUT;
    for (int xx = xg; xx <= 64; xx += 8) {
        float E = yr[0], O = 0.f;
        const float4* T = &T3[xx * 8];
        #pragma unroll
        for (int j = 0; j < 8; ++j) {
            float4 w = T[j];            // warp-uniform broadcast, imm offsets
            int ka = 2 * j + 1, kb = 2 * j + 2;
            E += yr[ka] * w.x;  O -= yi[ka] * w.y;
            E += yr[kb] * w.z;  O -= yi[kb] * w.w;
        }
        orow[(size_t)xx * COUT + o] = E + O;
        if (xx >= 1 && xx < 64)
            orow[(size_t)(128 - xx) * COUT + o] = E - O;
    }
}

// ---------------------------------------------------------------------------
extern "C" void kernel_launch(void* const* d_in, const int* in_sizes, int n_in,
                              void* d_out, int out_size) {
    const float* x     = (const float*)d_in[0];
    const float* t_emb = (const float*)d_in[1];
    const float* w1r   = (const float*)d_in[2];
    const float* w1i   = (const float*)d_in[3];
    const float* w2r   = (const float*)d_in[4];
    const float* w2i   = (const float*)d_in[5];
    const float* k1r   = (const float*)d_in[6];
    const float* k1i   = (const float*)d_in[7];
    const float* k2r   = (const float*)d_in[8];
    const float* k2i   = (const float*)d_in[9];
    float* out = (float*)d_out;

    cudaFuncSetAttribute(k2_mid, cudaFuncAttributeMaxDynamicSharedMemorySize,
                         K2_SMEM_BYTES);

    k_tables <<<32, 256>>>();
    k0_tscale<<<NB, 64>>>(t_emb, k1r, k1i, k2r, k2i);
    k1_dftx  <<<NB * GRID_N, 288>>>(x);
    k2_mid   <<<NB * MM, 288, K2_SMEM_BYTES>>>(w1r, w1i, w2r, w2i);
    k3_idftx <<<NB * GRID_N, 256>>>(out);
}